// round 2
// baseline (speedup 1.0000x reference)
#include <cuda_runtime.h>
#include <math.h>

#define BB 4
#define TT 2048
#define CC 1024
#define NH 16
#define HD 64
#define BT (BB*TT)      // 8192
#define C3 (3*CC)       // 3072

// Scratch (device globals; no allocation allowed)
__device__ float g_qkv[BT * C3];   // [BT, 3C]
__device__ float g_q[BT * CC];     // [B,H,T,64]
__device__ float g_k[BT * CC];
__device__ float g_v[BT * CC];
__device__ float g_attn[BT * CC];  // [B,T,C]

// ---------------------------------------------------------------------------
// Classic 128x128x8 SGEMM, 256 threads, 8x8 per-thread register tile.
// Requires M%128==0, N%128==0, K%8==0 (true for all shapes here).
// ---------------------------------------------------------------------------
__global__ __launch_bounds__(256) void sgemm_kernel(
    const float* __restrict__ A, const float* __restrict__ Bm,
    float* __restrict__ Cm, int M, int N, int K)
{
    __shared__ float As[8][128];
    __shared__ float Bs[8][128];

    int tid = threadIdx.x;
    int bm = blockIdx.y, bn = blockIdx.x;
    const float* Ab = A + (size_t)bm * 128 * K;
    const float* Bb = Bm + bn * 128;

    int arow = tid >> 1;            // 0..127
    int acol = (tid & 1) * 4;       // 0 or 4
    int brow = tid >> 5;            // 0..7
    int bcol = (tid & 31) * 4;      // 0..124

    int tx = tid & 15, ty = tid >> 4;

    float acc[8][8];
    #pragma unroll
    for (int i = 0; i < 8; i++)
        #pragma unroll
        for (int j = 0; j < 8; j++) acc[i][j] = 0.f;

    for (int k0 = 0; k0 < K; k0 += 8) {
        float4 av = *(const float4*)(Ab + (size_t)arow * K + k0 + acol);
        As[acol + 0][arow] = av.x;
        As[acol + 1][arow] = av.y;
        As[acol + 2][arow] = av.z;
        As[acol + 3][arow] = av.w;
        *(float4*)(&Bs[brow][bcol]) =
            *(const float4*)(Bb + (size_t)(k0 + brow) * N + bcol);
        __syncthreads();

        #pragma unroll
        for (int k = 0; k < 8; k++) {
            float ar[8], br[8];
            *(float4*)(ar)     = *(float4*)(&As[k][ty * 8]);
            *(float4*)(ar + 4) = *(float4*)(&As[k][ty * 8 + 4]);
            *(float4*)(br)     = *(float4*)(&Bs[k][tx * 8]);
            *(float4*)(br + 4) = *(float4*)(&Bs[k][tx * 8 + 4]);
            #pragma unroll
            for (int i = 0; i < 8; i++)
                #pragma unroll
                for (int j = 0; j < 8; j++)
                    acc[i][j] = fmaf(ar[i], br[j], acc[i][j]);
        }
        __syncthreads();
    }

    #pragma unroll
    for (int i = 0; i < 8; i++) {
        int row = bm * 128 + ty * 8 + i;
        float* crow = Cm + (size_t)row * N + bn * 128 + tx * 8;
        *(float4*)(crow)     = make_float4(acc[i][0], acc[i][1], acc[i][2], acc[i][3]);
        *(float4*)(crow + 4) = make_float4(acc[i][4], acc[i][5], acc[i][6], acc[i][7]);
    }
}

// ---------------------------------------------------------------------------
// Split qkv -> q,k,v in [B,H,T,64] layout; apply RoPE to q,k.
// One thread per (b,h,t,jj) with jj in [0,32).
// ---------------------------------------------------------------------------
__global__ void rope_split_kernel()
{
    int idx = blockIdx.x * blockDim.x + threadIdx.x;
    const int total = BB * NH * TT * 32;
    if (idx >= total) return;

    int jj = idx & 31;
    int tmp = idx >> 5;
    int t = tmp & (TT - 1);
    tmp >>= 11;                      // / TT
    int h = tmp & (NH - 1);
    int b = tmp >> 4;                // / NH

    // theta = t / 10000^(2*jj/64)
    const float LOG1E4 = 9.210340371976184f;  // ln(10000)
    float inv_freq = expf(-(float)jj * (LOG1E4 / 32.0f));
    float ang = (float)t * inv_freq;
    float cs = cosf(ang), sn = sinf(ang);

    size_t src_row = (size_t)(b * TT + t) * C3;
    int col = h * HD + jj;

    float q1 = g_qkv[src_row + col];
    float q2 = g_qkv[src_row + col + 32];
    float k1 = g_qkv[src_row + CC + col];
    float k2 = g_qkv[src_row + CC + col + 32];
    float v1 = g_qkv[src_row + 2 * CC + col];
    float v2 = g_qkv[src_row + 2 * CC + col + 32];

    size_t dst = ((size_t)(b * NH + h) * TT + t) * HD + jj;
    g_q[dst]      = q1 * cs - q2 * sn;
    g_q[dst + 32] = q2 * cs + q1 * sn;
    g_k[dst]      = k1 * cs - k2 * sn;
    g_k[dst + 32] = k2 * cs + k1 * sn;
    g_v[dst]      = v1;
    g_v[dst + 32] = v2;
}

// ---------------------------------------------------------------------------
// Flash attention (causal). One CTA = 64 queries of one (b,h).
// 256 threads (16x16), 4x4 register tiles for both matmuls.
// Dynamic smem layout (floats):
//   sQ[64*64] | sK[64*65] | sV[64*64] | sS[64*65] | m[64] | l[64] | corr[64]
// ---------------------------------------------------------------------------
#define SQ_OFF   0
#define SK_OFF   (64*64)
#define SV_OFF   (SK_OFF + 64*65)
#define SS_OFF   (SV_OFF + 64*64)
#define SM_OFF   (SS_OFF + 64*65)
#define SL_OFF   (SM_OFF + 64)
#define SC_OFF   (SL_OFF + 64)
#define ATTN_SMEM_FLOATS (SC_OFF + 64)

__global__ __launch_bounds__(256) void attn_kernel()
{
    extern __shared__ float sh[];
    float* sQ = sh + SQ_OFF;
    float* sK = sh + SK_OFF;
    float* sV = sh + SV_OFF;
    float* sS = sh + SS_OFF;
    float* rm = sh + SM_OFF;
    float* rl = sh + SL_OFF;
    float* rc = sh + SC_OFF;

    int tid = threadIdx.x;
    int qb = blockIdx.x;       // query block 0..31
    int bh = blockIdx.y;       // b*NH + h

    const float* Qg = g_q + ((size_t)bh * TT + qb * 64) * HD;
    const float* Kg = g_k + (size_t)bh * TT * HD;
    const float* Vg = g_v + (size_t)bh * TT * HD;

    // load Q tile
    for (int i = tid * 4; i < 4096; i += 1024)
        *(float4*)(sQ + i) = *(const float4*)(Qg + i);
    if (tid < 64) { rm[tid] = -1e30f; rl[tid] = 0.f; }

    int tx = tid & 15, ty = tid >> 4;
    int r0 = ty * 4, c0 = tx * 4;
    float o[4][4];
    #pragma unroll
    for (int i = 0; i < 4; i++)
        #pragma unroll
        for (int j = 0; j < 4; j++) o[i][j] = 0.f;

    for (int kb = 0; kb <= qb; kb++) {
        __syncthreads();   // prev iteration done with sK/sV/sS; first iter: Q ready
        for (int i = tid * 4; i < 4096; i += 1024) {
            int row = i >> 6, col = i & 63;
            // sK has 65-float row stride -> NOT 16B aligned per row; store scalars.
            float4 kv = *(const float4*)(Kg + kb * 4096 + i);
            float* krow = sK + row * 65 + col;
            krow[0] = kv.x; krow[1] = kv.y; krow[2] = kv.z; krow[3] = kv.w;
            *(float4*)(sV + i) = *(const float4*)(Vg + kb * 4096 + i);
        }
        __syncthreads();

        // S = (Q K^T) / 8
        float s[4][4];
        #pragma unroll
        for (int i = 0; i < 4; i++)
            #pragma unroll
            for (int j = 0; j < 4; j++) s[i][j] = 0.f;
        #pragma unroll 4
        for (int k = 0; k < 64; k++) {
            float a0 = sQ[(r0 + 0) * 64 + k];
            float a1 = sQ[(r0 + 1) * 64 + k];
            float a2 = sQ[(r0 + 2) * 64 + k];
            float a3 = sQ[(r0 + 3) * 64 + k];
            float b0 = sK[(c0 + 0) * 65 + k];
            float b1 = sK[(c0 + 1) * 65 + k];
            float b2 = sK[(c0 + 2) * 65 + k];
            float b3 = sK[(c0 + 3) * 65 + k];
            s[0][0] = fmaf(a0, b0, s[0][0]); s[0][1] = fmaf(a0, b1, s[0][1]);
            s[0][2] = fmaf(a0, b2, s[0][2]); s[0][3] = fmaf(a0, b3, s[0][3]);
            s[1][0] = fmaf(a1, b0, s[1][0]); s[1][1] = fmaf(a1, b1, s[1][1]);
            s[1][2] = fmaf(a1, b2, s[1][2]); s[1][3] = fmaf(a1, b3, s[1][3]);
            s[2][0] = fmaf(a2, b0, s[2][0]); s[2][1] = fmaf(a2, b1, s[2][1]);
            s[2][2] = fmaf(a2, b2, s[2][2]); s[2][3] = fmaf(a2, b3, s[2][3]);
            s[3][0] = fmaf(a3, b0, s[3][0]); s[3][1] = fmaf(a3, b1, s[3][1]);
            s[3][2] = fmaf(a3, b2, s[3][2]); s[3][3] = fmaf(a3, b3, s[3][3]);
        }
        bool diag = (kb == qb);
        #pragma unroll
        for (int i = 0; i < 4; i++)
            #pragma unroll
            for (int j = 0; j < 4; j++) {
                float v = s[i][j] * 0.125f;
                if (diag && (c0 + j > r0 + i)) v = -1e30f;
                sS[(r0 + i) * 65 + (c0 + j)] = v;
            }
        __syncthreads();

        // online softmax per row (64 row-threads)
        if (tid < 64) {
            int r = tid;
            float m_old = rm[r];
            float mx = m_old;
            #pragma unroll 8
            for (int j = 0; j < 64; j++) mx = fmaxf(mx, sS[r * 65 + j]);
            float corr = __expf(m_old - mx);
            float l = rl[r] * corr;
            #pragma unroll 8
            for (int j = 0; j < 64; j++) {
                float p = __expf(sS[r * 65 + j] - mx);
                sS[r * 65 + j] = p;
                l += p;
            }
            rm[r] = mx; rl[r] = l; rc[r] = corr;
        }
        __syncthreads();

        // O = O*corr + P @ V
        float cr[4];
        #pragma unroll
        for (int i = 0; i < 4; i++) cr[i] = rc[r0 + i];
        #pragma unroll
        for (int i = 0; i < 4; i++)
            #pragma unroll
            for (int j = 0; j < 4; j++) o[i][j] *= cr[i];
        #pragma unroll 4
        for (int k = 0; k < 64; k++) {
            float p0 = sS[(r0 + 0) * 65 + k];
            float p1 = sS[(r0 + 1) * 65 + k];
            float p2 = sS[(r0 + 2) * 65 + k];
            float p3 = sS[(r0 + 3) * 65 + k];
            float4 vv = *(float4*)(sV + k * 64 + c0);
            o[0][0] = fmaf(p0, vv.x, o[0][0]); o[0][1] = fmaf(p0, vv.y, o[0][1]);
            o[0][2] = fmaf(p0, vv.z, o[0][2]); o[0][3] = fmaf(p0, vv.w, o[0][3]);
            o[1][0] = fmaf(p1, vv.x, o[1][0]); o[1][1] = fmaf(p1, vv.y, o[1][1]);
            o[1][2] = fmaf(p1, vv.z, o[1][2]); o[1][3] = fmaf(p1, vv.w, o[1][3]);
            o[2][0] = fmaf(p2, vv.x, o[2][0]); o[2][1] = fmaf(p2, vv.y, o[2][1]);
            o[2][2] = fmaf(p2, vv.z, o[2][2]); o[2][3] = fmaf(p2, vv.w, o[2][3]);
            o[3][0] = fmaf(p3, vv.x, o[3][0]); o[3][1] = fmaf(p3, vv.y, o[3][1]);
            o[3][2] = fmaf(p3, vv.z, o[3][2]); o[3][3] = fmaf(p3, vv.w, o[3][3]);
        }
    }

    // write normalized O into [B,T,C] layout
    int b = bh >> 4;          // / NH
    int h = bh & (NH - 1);
    #pragma unroll
    for (int i = 0; i < 4; i++) {
        float inv_l = 1.f / rl[r0 + i];
        int t = qb * 64 + r0 + i;
        float* dst = g_attn + ((size_t)(b * TT + t)) * CC + h * HD + c0;
        dst[0] = o[i][0] * inv_l;
        dst[1] = o[i][1] * inv_l;
        dst[2] = o[i][2] * inv_l;
        dst[3] = o[i][3] * inv_l;
    }
}

// ---------------------------------------------------------------------------
extern "C" void kernel_launch(void* const* d_in, const int* in_sizes, int n_in,
                              void* d_out, int out_size)
{
    const float* x     = (const float*)d_in[0];
    const float* w_qkv = (const float*)d_in[1];
    const float* w_out = (const float*)d_in[2];
    float* out = (float*)d_out;

    float *qkv_p, *attn_p;
    cudaGetSymbolAddress((void**)&qkv_p,  g_qkv);
    cudaGetSymbolAddress((void**)&attn_p, g_attn);

    // 1) QKV projection: [8192,1024] @ [1024,3072]
    {
        dim3 grid(C3 / 128, BT / 128);
        sgemm_kernel<<<grid, 256>>>(x, w_qkv, qkv_p, BT, C3, CC);
    }

    // 2) split + RoPE
    {
        int total = BB * NH * TT * 32;
        rope_split_kernel<<<(total + 255) / 256, 256>>>();
    }

    // 3) flash attention
    {
        int smem_bytes = ATTN_SMEM_FLOATS * sizeof(float);
        cudaFuncSetAttribute(attn_kernel,
                             cudaFuncAttributeMaxDynamicSharedMemorySize,
                             smem_bytes);
        dim3 grid(TT / 64, BB * NH);
        attn_kernel<<<grid, 256, smem_bytes>>>();
    }

    // 4) output projection: [8192,1024] @ [1024,1024]
    {
        dim3 grid(CC / 128, BT / 128);
        sgemm_kernel<<<grid, 256>>>(attn_p, w_out, out, BT, CC, CC);
    }
}

// round 3
// speedup vs baseline: 1.7181x; 1.7181x over previous
#include <cuda_runtime.h>
#include <math.h>

#define BB 4
#define TT 2048
#define CC 1024
#define NH 16
#define HD 64
#define BT (BB*TT)      // 8192
#define C3 (3*CC)       // 3072

// Scratch (device globals; no allocation allowed)
__device__ float g_qkv[BT * C3];   // [BT, 3C]
__device__ float g_q[BT * CC];     // [B,H,T,64]
__device__ float g_k[BT * CC];
__device__ float g_v[BT * CC];
__device__ float g_attn[BT * CC];  // [B,T,C]

// ---------------------------------------------------------------------------
// Classic 128x128x8 SGEMM, 256 threads, 8x8 per-thread register tile.
// ---------------------------------------------------------------------------
__global__ __launch_bounds__(256) void sgemm_kernel(
    const float* __restrict__ A, const float* __restrict__ Bm,
    float* __restrict__ Cm, int M, int N, int K)
{
    __shared__ float As[8][128];
    __shared__ float Bs[8][128];

    int tid = threadIdx.x;
    int bm = blockIdx.y, bn = blockIdx.x;
    const float* Ab = A + (size_t)bm * 128 * K;
    const float* Bb = Bm + bn * 128;

    int arow = tid >> 1;            // 0..127
    int acol = (tid & 1) * 4;       // 0 or 4
    int brow = tid >> 5;            // 0..7
    int bcol = (tid & 31) * 4;      // 0..124

    int tx = tid & 15, ty = tid >> 4;

    float acc[8][8];
    #pragma unroll
    for (int i = 0; i < 8; i++)
        #pragma unroll
        for (int j = 0; j < 8; j++) acc[i][j] = 0.f;

    for (int k0 = 0; k0 < K; k0 += 8) {
        float4 av = *(const float4*)(Ab + (size_t)arow * K + k0 + acol);
        As[acol + 0][arow] = av.x;
        As[acol + 1][arow] = av.y;
        As[acol + 2][arow] = av.z;
        As[acol + 3][arow] = av.w;
        *(float4*)(&Bs[brow][bcol]) =
            *(const float4*)(Bb + (size_t)(k0 + brow) * N + bcol);
        __syncthreads();

        #pragma unroll
        for (int k = 0; k < 8; k++) {
            float ar[8], br[8];
            *(float4*)(ar)     = *(float4*)(&As[k][ty * 8]);
            *(float4*)(ar + 4) = *(float4*)(&As[k][ty * 8 + 4]);
            *(float4*)(br)     = *(float4*)(&Bs[k][tx * 8]);
            *(float4*)(br + 4) = *(float4*)(&Bs[k][tx * 8 + 4]);
            #pragma unroll
            for (int i = 0; i < 8; i++)
                #pragma unroll
                for (int j = 0; j < 8; j++)
                    acc[i][j] = fmaf(ar[i], br[j], acc[i][j]);
        }
        __syncthreads();
    }

    #pragma unroll
    for (int i = 0; i < 8; i++) {
        int row = bm * 128 + ty * 8 + i;
        float* crow = Cm + (size_t)row * N + bn * 128 + tx * 8;
        *(float4*)(crow)     = make_float4(acc[i][0], acc[i][1], acc[i][2], acc[i][3]);
        *(float4*)(crow + 4) = make_float4(acc[i][4], acc[i][5], acc[i][6], acc[i][7]);
    }
}

// ---------------------------------------------------------------------------
// Split qkv -> q,k,v in [B,H,T,64] layout; apply RoPE to q,k.
// ---------------------------------------------------------------------------
__global__ void rope_split_kernel()
{
    int idx = blockIdx.x * blockDim.x + threadIdx.x;
    const int total = BB * NH * TT * 32;
    if (idx >= total) return;

    int jj = idx & 31;
    int tmp = idx >> 5;
    int t = tmp & (TT - 1);
    tmp >>= 11;
    int h = tmp & (NH - 1);
    int b = tmp >> 4;

    const float LOG1E4 = 9.210340371976184f;  // ln(10000)
    float inv_freq = expf(-(float)jj * (LOG1E4 / 32.0f));
    float ang = (float)t * inv_freq;
    float cs = cosf(ang), sn = sinf(ang);

    size_t src_row = (size_t)(b * TT + t) * C3;
    int col = h * HD + jj;

    float q1 = g_qkv[src_row + col];
    float q2 = g_qkv[src_row + col + 32];
    float k1 = g_qkv[src_row + CC + col];
    float k2 = g_qkv[src_row + CC + col + 32];
    float v1 = g_qkv[src_row + 2 * CC + col];
    float v2 = g_qkv[src_row + 2 * CC + col + 32];

    size_t dst = ((size_t)(b * NH + h) * TT + t) * HD + jj;
    g_q[dst]      = q1 * cs - q2 * sn;
    g_q[dst + 32] = q2 * cs + q1 * sn;
    g_k[dst]      = k1 * cs - k2 * sn;
    g_k[dst + 32] = k2 * cs + k1 * sn;
    g_v[dst]      = v1;
    g_v[dst + 32] = v2;
}

// ---------------------------------------------------------------------------
// Flash attention (causal), v2: fully parallel softmax.
// One CTA = 64 queries of one (b,h). 256 threads (16x16), 4x4 reg tiles.
// Row r is owned by the 16 threads with ty == r/4; these are lanes [0..15]
// or [16..31] of a warp, so xor-shuffles with masks 1,2,4,8 reduce over
// exactly one row group. m/l live in registers (replicated across the group).
// Smem (floats): sQ[64*64] | sK[64*65] | sV[64*64] | sS[64*68]
// ---------------------------------------------------------------------------
#define SQ_OFF   0
#define SK_OFF   (64*64)
#define SV_OFF   (SK_OFF + 64*65)
#define SS_OFF   (SV_OFF + 64*64)
#define ATTN_SMEM_FLOATS (SS_OFF + 64*68)

__global__ __launch_bounds__(256) void attn_kernel()
{
    extern __shared__ float sh[];
    float* sQ = sh + SQ_OFF;
    float* sK = sh + SK_OFF;
    float* sV = sh + SV_OFF;
    float* sS = sh + SS_OFF;

    int tid = threadIdx.x;
    int qb = blockIdx.x;       // query block 0..31
    int bh = blockIdx.y;       // b*NH + h

    const float* Qg = g_q + ((size_t)bh * TT + qb * 64) * HD;
    const float* Kg = g_k + (size_t)bh * TT * HD;
    const float* Vg = g_v + (size_t)bh * TT * HD;

    // load Q tile, folding in the 1/sqrt(d)=1/8 scale
    for (int i = tid * 4; i < 4096; i += 1024) {
        float4 qv = *(const float4*)(Qg + i);
        qv.x *= 0.125f; qv.y *= 0.125f; qv.z *= 0.125f; qv.w *= 0.125f;
        *(float4*)(sQ + i) = qv;
    }

    int tx = tid & 15, ty = tid >> 4;
    int r0 = ty * 4, c0 = tx * 4;

    float o[4][4];
    float rm[4], rl[4];
    #pragma unroll
    for (int i = 0; i < 4; i++) {
        rm[i] = -1e30f; rl[i] = 0.f;
        #pragma unroll
        for (int j = 0; j < 4; j++) o[i][j] = 0.f;
    }

    for (int kb = 0; kb <= qb; kb++) {
        __syncthreads();   // prev iter done with sK/sV/sS; first iter: Q loads visible
        for (int i = tid * 4; i < 4096; i += 1024) {
            int row = i >> 6, col = i & 63;
            float4 kv = *(const float4*)(Kg + kb * 4096 + i);
            float* krow = sK + row * 65 + col;   // 65-stride: scalar stores
            krow[0] = kv.x; krow[1] = kv.y; krow[2] = kv.z; krow[3] = kv.w;
            *(float4*)(sV + i) = *(const float4*)(Vg + kb * 4096 + i);
        }
        __syncthreads();

        // S = Q K^T (Q pre-scaled)
        float s[4][4];
        #pragma unroll
        for (int i = 0; i < 4; i++)
            #pragma unroll
            for (int j = 0; j < 4; j++) s[i][j] = 0.f;
        #pragma unroll 4
        for (int k = 0; k < 64; k++) {
            float a0 = sQ[(r0 + 0) * 64 + k];
            float a1 = sQ[(r0 + 1) * 64 + k];
            float a2 = sQ[(r0 + 2) * 64 + k];
            float a3 = sQ[(r0 + 3) * 64 + k];
            float b0 = sK[(c0 + 0) * 65 + k];
            float b1 = sK[(c0 + 1) * 65 + k];
            float b2 = sK[(c0 + 2) * 65 + k];
            float b3 = sK[(c0 + 3) * 65 + k];
            s[0][0] = fmaf(a0, b0, s[0][0]); s[0][1] = fmaf(a0, b1, s[0][1]);
            s[0][2] = fmaf(a0, b2, s[0][2]); s[0][3] = fmaf(a0, b3, s[0][3]);
            s[1][0] = fmaf(a1, b0, s[1][0]); s[1][1] = fmaf(a1, b1, s[1][1]);
            s[1][2] = fmaf(a1, b2, s[1][2]); s[1][3] = fmaf(a1, b3, s[1][3]);
            s[2][0] = fmaf(a2, b0, s[2][0]); s[2][1] = fmaf(a2, b1, s[2][1]);
            s[2][2] = fmaf(a2, b2, s[2][2]); s[2][3] = fmaf(a2, b3, s[2][3]);
            s[3][0] = fmaf(a3, b0, s[3][0]); s[3][1] = fmaf(a3, b1, s[3][1]);
            s[3][2] = fmaf(a3, b2, s[3][2]); s[3][3] = fmaf(a3, b3, s[3][3]);
        }

        if (kb == qb) {   // causal mask on the diagonal tile
            #pragma unroll
            for (int i = 0; i < 4; i++)
                #pragma unroll
                for (int j = 0; j < 4; j++)
                    if (c0 + j > r0 + i) s[i][j] = -1e30f;
        }

        // online softmax, all threads, shuffle reductions over 16-lane groups
        #pragma unroll
        for (int i = 0; i < 4; i++) {
            float mx = fmaxf(fmaxf(s[i][0], s[i][1]), fmaxf(s[i][2], s[i][3]));
            #pragma unroll
            for (int m = 8; m >= 1; m >>= 1)
                mx = fmaxf(mx, __shfl_xor_sync(0xffffffffu, mx, m));
            float mnew = fmaxf(rm[i], mx);
            float corr = __expf(rm[i] - mnew);
            rm[i] = mnew;
            float sum = 0.f;
            #pragma unroll
            for (int j = 0; j < 4; j++) {
                float p = __expf(s[i][j] - mnew);
                s[i][j] = p;
                sum += p;
            }
            #pragma unroll
            for (int m = 8; m >= 1; m >>= 1)
                sum += __shfl_xor_sync(0xffffffffu, sum, m);
            rl[i] = rl[i] * corr + sum;
            #pragma unroll
            for (int j = 0; j < 4; j++) o[i][j] *= corr;
        }

        // publish P (stride 68: float4-aligned stores, conflict-free reads)
        #pragma unroll
        for (int i = 0; i < 4; i++)
            *(float4*)(sS + (r0 + i) * 68 + c0) =
                make_float4(s[i][0], s[i][1], s[i][2], s[i][3]);
        __syncthreads();

        // O += P @ V
        #pragma unroll 4
        for (int k = 0; k < 64; k++) {
            float p0 = sS[(r0 + 0) * 68 + k];
            float p1 = sS[(r0 + 1) * 68 + k];
            float p2 = sS[(r0 + 2) * 68 + k];
            float p3 = sS[(r0 + 3) * 68 + k];
            float4 vv = *(float4*)(sV + k * 64 + c0);
            o[0][0] = fmaf(p0, vv.x, o[0][0]); o[0][1] = fmaf(p0, vv.y, o[0][1]);
            o[0][2] = fmaf(p0, vv.z, o[0][2]); o[0][3] = fmaf(p0, vv.w, o[0][3]);
            o[1][0] = fmaf(p1, vv.x, o[1][0]); o[1][1] = fmaf(p1, vv.y, o[1][1]);
            o[1][2] = fmaf(p1, vv.z, o[1][2]); o[1][3] = fmaf(p1, vv.w, o[1][3]);
            o[2][0] = fmaf(p2, vv.x, o[2][0]); o[2][1] = fmaf(p2, vv.y, o[2][1]);
            o[2][2] = fmaf(p2, vv.z, o[2][2]); o[2][3] = fmaf(p2, vv.w, o[2][3]);
            o[3][0] = fmaf(p3, vv.x, o[3][0]); o[3][1] = fmaf(p3, vv.y, o[3][1]);
            o[3][2] = fmaf(p3, vv.z, o[3][2]); o[3][3] = fmaf(p3, vv.w, o[3][3]);
        }
    }

    // write normalized O into [B,T,C] layout
    int b = bh >> 4;
    int h = bh & (NH - 1);
    #pragma unroll
    for (int i = 0; i < 4; i++) {
        float inv_l = 1.f / rl[i];
        int t = qb * 64 + r0 + i;
        float* dst = g_attn + ((size_t)(b * TT + t)) * CC + h * HD + c0;
        dst[0] = o[i][0] * inv_l;
        dst[1] = o[i][1] * inv_l;
        dst[2] = o[i][2] * inv_l;
        dst[3] = o[i][3] * inv_l;
    }
}

// ---------------------------------------------------------------------------
extern "C" void kernel_launch(void* const* d_in, const int* in_sizes, int n_in,
                              void* d_out, int out_size)
{
    const float* x     = (const float*)d_in[0];
    const float* w_qkv = (const float*)d_in[1];
    const float* w_out = (const float*)d_in[2];
    float* out = (float*)d_out;

    float *qkv_p, *attn_p;
    cudaGetSymbolAddress((void**)&qkv_p,  g_qkv);
    cudaGetSymbolAddress((void**)&attn_p, g_attn);

    // 1) QKV projection: [8192,1024] @ [1024,3072]
    {
        dim3 grid(C3 / 128, BT / 128);
        sgemm_kernel<<<grid, 256>>>(x, w_qkv, qkv_p, BT, C3, CC);
    }

    // 2) split + RoPE
    {
        int total = BB * NH * TT * 32;
        rope_split_kernel<<<(total + 255) / 256, 256>>>();
    }

    // 3) flash attention
    {
        int smem_bytes = ATTN_SMEM_FLOATS * sizeof(float);
        cudaFuncSetAttribute(attn_kernel,
                             cudaFuncAttributeMaxDynamicSharedMemorySize,
                             smem_bytes);
        dim3 grid(TT / 64, BB * NH);
        attn_kernel<<<grid, 256, smem_bytes>>>();
    }

    // 4) output projection: [8192,1024] @ [1024,1024]
    {
        dim3 grid(CC / 128, BT / 128);
        sgemm_kernel<<<grid, 256>>>(attn_p, w_out, out, BT, CC, CC);
    }
}

// round 4
// speedup vs baseline: 5.1743x; 3.0116x over previous
#include <cuda_runtime.h>
#include <math.h>

#define BB 4
#define TT 2048
#define CC 1024
#define NH 16
#define HD 64
#define BT (BB*TT)      // 8192
#define C3 (3*CC)       // 3072

// Scratch (device globals; no allocation allowed)
__device__ float g_qkv[BT * C3];   // [BT, 3C]
__device__ float g_q[BT * CC];     // [B,H,T,64]
__device__ float g_k[BT * CC];
__device__ float g_v[BT * CC];
__device__ float g_attn[BT * CC];  // [B,T,C]

// ---------------------------------------------------------------------------
// helpers
// ---------------------------------------------------------------------------
__device__ __forceinline__ unsigned f2tf(float x) {
    unsigned r;
    asm("cvt.rna.tf32.f32 %0, %1;" : "=r"(r) : "f"(x));
    return r;
}

// D = A(16x8) * B(8x8) + D  (tf32 in, fp32 accum), row.col
__device__ __forceinline__ void mma8(float* c, const unsigned* a,
                                     unsigned b0, unsigned b1) {
    asm("mma.sync.aligned.m16n8k8.row.col.f32.tf32.tf32.f32 "
        "{%0,%1,%2,%3}, {%4,%5,%6,%7}, {%8,%9}, {%0,%1,%2,%3};"
        : "+f"(c[0]), "+f"(c[1]), "+f"(c[2]), "+f"(c[3])
        : "r"(a[0]), "r"(a[1]), "r"(a[2]), "r"(a[3]), "r"(b0), "r"(b1));
}

// ---------------------------------------------------------------------------
// tf32 tensor-core GEMM: C[M,N] = A[M,K] @ B[K,N], tiles 128x128x16.
// 256 threads = 8 warps in 2(m) x 4(n); warp tile 64x32 = 4x4 m16n8 tiles.
// As: [k][m] stride 136, m XOR-swizzled by 8*((k>>2)&3)  -> conflict-free
// Bs: [k][n] stride 136 (plain)                          -> conflict-free
// ---------------------------------------------------------------------------
__global__ __launch_bounds__(256) void gemm_tf32(
    const float* __restrict__ A, const float* __restrict__ Bm,
    float* __restrict__ Cm, int M, int N, int K)
{
    __shared__ unsigned As[16 * 136];
    __shared__ unsigned Bs[16 * 136];

    int tid = threadIdx.x;
    int lane = tid & 31;
    int warp = tid >> 5;
    int gid = lane >> 2, tig = lane & 3;
    int warp_m = warp >> 2, warp_n = warp & 3;
    int bm = blockIdx.y, bn = blockIdx.x;

    const float* Abase = A + (size_t)(bm * 128) * K;
    const float* Bbase = Bm + (size_t)bn * 128;

    float acc[4][4][4];
    #pragma unroll
    for (int mt = 0; mt < 4; mt++)
        #pragma unroll
        for (int nt = 0; nt < 4; nt++)
            #pragma unroll
            for (int e = 0; e < 4; e++) acc[mt][nt][e] = 0.f;

    int am = tid >> 2;            // 0..63  (rows 0..63; +64 for second load)
    int af4 = tid & 3;            // k-group
    int bk = tid >> 5;            // 0..7
    int bn4 = (tid & 31) * 4;

    for (int k0 = 0; k0 < K; k0 += 16) {
        float4 a0v = *(const float4*)(Abase + (size_t)am * K + k0 + af4 * 4);
        float4 a1v = *(const float4*)(Abase + (size_t)(am + 64) * K + k0 + af4 * 4);
        float4 b0v = *(const float4*)(Bbase + (size_t)(k0 + bk) * N + bn4);
        float4 b1v = *(const float4*)(Bbase + (size_t)(k0 + bk + 8) * N + bn4);
        __syncthreads();
        {
            int swz = 8 * af4;                    // (k>>2)&3 == af4 for k=4*af4+i
            int kb4 = af4 * 4;
            As[(kb4 + 0) * 136 + (am ^ swz)] = f2tf(a0v.x);
            As[(kb4 + 1) * 136 + (am ^ swz)] = f2tf(a0v.y);
            As[(kb4 + 2) * 136 + (am ^ swz)] = f2tf(a0v.z);
            As[(kb4 + 3) * 136 + (am ^ swz)] = f2tf(a0v.w);
            int am2 = am + 64;
            As[(kb4 + 0) * 136 + (am2 ^ swz)] = f2tf(a1v.x);
            As[(kb4 + 1) * 136 + (am2 ^ swz)] = f2tf(a1v.y);
            As[(kb4 + 2) * 136 + (am2 ^ swz)] = f2tf(a1v.z);
            As[(kb4 + 3) * 136 + (am2 ^ swz)] = f2tf(a1v.w);

            uint4 t0 = make_uint4(f2tf(b0v.x), f2tf(b0v.y), f2tf(b0v.z), f2tf(b0v.w));
            uint4 t1 = make_uint4(f2tf(b1v.x), f2tf(b1v.y), f2tf(b1v.z), f2tf(b1v.w));
            *(uint4*)&Bs[bk * 136 + bn4] = t0;
            *(uint4*)&Bs[(bk + 8) * 136 + bn4] = t1;
        }
        __syncthreads();

        #pragma unroll
        for (int ks = 0; ks < 16; ks += 8) {
            unsigned afr[4][4];
            unsigned bfr[4][2];
            int swz1 = 8 * ((ks >> 2) & 3);       // rows ks..ks+3
            int swz2 = 8 * (((ks + 4) >> 2) & 3); // rows ks+4..ks+7
            #pragma unroll
            for (int mt = 0; mt < 4; mt++) {
                int m = warp_m * 64 + mt * 16 + gid;
                afr[mt][0] = As[(ks + tig) * 136 + (m ^ swz1)];
                afr[mt][1] = As[(ks + tig) * 136 + ((m + 8) ^ swz1)];
                afr[mt][2] = As[(ks + tig + 4) * 136 + (m ^ swz2)];
                afr[mt][3] = As[(ks + tig + 4) * 136 + ((m + 8) ^ swz2)];
            }
            #pragma unroll
            for (int nt = 0; nt < 4; nt++) {
                int n = warp_n * 32 + nt * 8 + gid;
                bfr[nt][0] = Bs[(ks + tig) * 136 + n];
                bfr[nt][1] = Bs[(ks + tig + 4) * 136 + n];
            }
            #pragma unroll
            for (int mt = 0; mt < 4; mt++)
                #pragma unroll
                for (int nt = 0; nt < 4; nt++)
                    mma8(acc[mt][nt], afr[mt], bfr[nt][0], bfr[nt][1]);
        }
    }

    #pragma unroll
    for (int mt = 0; mt < 4; mt++)
        #pragma unroll
        for (int nt = 0; nt < 4; nt++) {
            int row = bm * 128 + warp_m * 64 + mt * 16 + gid;
            int col = bn * 128 + warp_n * 32 + nt * 8 + tig * 2;
            *(float2*)&Cm[(size_t)row * N + col] =
                make_float2(acc[mt][nt][0], acc[mt][nt][1]);
            *(float2*)&Cm[(size_t)(row + 8) * N + col] =
                make_float2(acc[mt][nt][2], acc[mt][nt][3]);
        }
}

// ---------------------------------------------------------------------------
// Split qkv -> q,k,v in [B,H,T,64] layout; apply RoPE to q,k. (unchanged)
// ---------------------------------------------------------------------------
__global__ void rope_split_kernel()
{
    int idx = blockIdx.x * blockDim.x + threadIdx.x;
    const int total = BB * NH * TT * 32;
    if (idx >= total) return;

    int jj = idx & 31;
    int tmp = idx >> 5;
    int t = tmp & (TT - 1);
    tmp >>= 11;
    int h = tmp & (NH - 1);
    int b = tmp >> 4;

    const float LOG1E4 = 9.210340371976184f;
    float inv_freq = expf(-(float)jj * (LOG1E4 / 32.0f));
    float ang = (float)t * inv_freq;
    float cs = cosf(ang), sn = sinf(ang);

    size_t src_row = (size_t)(b * TT + t) * C3;
    int col = h * HD + jj;

    float q1 = g_qkv[src_row + col];
    float q2 = g_qkv[src_row + col + 32];
    float k1 = g_qkv[src_row + CC + col];
    float k2 = g_qkv[src_row + CC + col + 32];
    float v1 = g_qkv[src_row + 2 * CC + col];
    float v2 = g_qkv[src_row + 2 * CC + col + 32];

    size_t dst = ((size_t)(b * NH + h) * TT + t) * HD + jj;
    g_q[dst]      = q1 * cs - q2 * sn;
    g_q[dst + 32] = q2 * cs + q1 * sn;
    g_k[dst]      = k1 * cs - k2 * sn;
    g_k[dst + 32] = k2 * cs + k1 * sn;
    g_v[dst]      = v1;
    g_v[dst + 32] = v2;
}

// ---------------------------------------------------------------------------
// Flash attention (causal) on tensor cores, tf32 mma.
// CTA = 128 queries x kv-tiles of 64, one (b,h). 8 warps, warp w owns the
// m16 strip rows [16w,16w+16). Softmax reductions within 4-lane quads.
// Smem (uint32):
//   sQ [64][136]  (d, q)     tf32, Q pre-scaled by 0.125
//   sP [64][136]  (kv, q)    tf32
//   sK [64][72]   (d, kv^swz(d))
//   sV [64][72]   (kv, d^swz(kv))     swz(i) = ((i>>2)&7)<<2
// ---------------------------------------------------------------------------
#define AQ_STR 136
#define AK_STR 72
#define ATTN_SMEM_WORDS (2 * 64 * AQ_STR + 2 * 64 * AK_STR)

__global__ __launch_bounds__(256) void attn_mma_kernel()
{
    extern __shared__ unsigned sm[];
    unsigned* sQ = sm;
    unsigned* sP = sm + 64 * AQ_STR;
    unsigned* sK = sm + 2 * 64 * AQ_STR;
    unsigned* sV = sK + 64 * AK_STR;

    int tid = threadIdx.x;
    int lane = tid & 31;
    int warp = tid >> 5;
    int gid = lane >> 2, tig = lane & 3;
    int qb = blockIdx.x;       // 0..15  (128 queries each)
    int bh = blockIdx.y;       // b*NH + h

    const float* Qg = g_q + ((size_t)bh * TT + qb * 128) * HD;
    const float* Kg = g_k + (size_t)bh * TT * HD;
    const float* Vg = g_v + (size_t)bh * TT * HD;

    // load Q (128x64) -> sQ[d][q], tf32, fold in 1/8 scale
    #pragma unroll
    for (int it = 0; it < 8; it++) {
        int fid = tid + 256 * it;
        int q = fid >> 4;
        int d0 = (fid & 15) * 4;
        float4 v = *(const float4*)(Qg + q * 64 + d0);
        sQ[(d0 + 0) * AQ_STR + q] = f2tf(v.x * 0.125f);
        sQ[(d0 + 1) * AQ_STR + q] = f2tf(v.y * 0.125f);
        sQ[(d0 + 2) * AQ_STR + q] = f2tf(v.z * 0.125f);
        sQ[(d0 + 3) * AQ_STR + q] = f2tf(v.w * 0.125f);
    }

    float oacc[8][4];
    #pragma unroll
    for (int nt = 0; nt < 8; nt++)
        #pragma unroll
        for (int e = 0; e < 4; e++) oacc[nt][e] = 0.f;
    float rm0 = -1e30f, rm1 = -1e30f, rl0 = 0.f, rl1 = 0.f;

    int m_local = warp * 16 + gid;           // query row (local), +8 for second
    int row1 = qb * 128 + m_local;           // global query rows
    int row2 = row1 + 8;

    int kb_max = 2 * qb + 1;
    for (int kb = 0; kb <= kb_max; kb++) {
        __syncthreads();
        // load K,V tile (64x64) with transpose/swizzle
        #pragma unroll
        for (int it = 0; it < 4; it++) {
            int fid = tid + 256 * it;
            int r = fid >> 4;                // kv row
            int d0 = (fid & 15) * 4;
            const float* kp = Kg + (size_t)(kb * 64 + r) * 64 + d0;
            float4 kv4 = *(const float4*)kp;
            sK[(d0 + 0) * AK_STR + (r ^ ((((d0 + 0) >> 2) & 7) << 2))] = f2tf(kv4.x);
            sK[(d0 + 1) * AK_STR + (r ^ ((((d0 + 1) >> 2) & 7) << 2))] = f2tf(kv4.y);
            sK[(d0 + 2) * AK_STR + (r ^ ((((d0 + 2) >> 2) & 7) << 2))] = f2tf(kv4.z);
            sK[(d0 + 3) * AK_STR + (r ^ ((((d0 + 3) >> 2) & 7) << 2))] = f2tf(kv4.w);
            const float* vp = Vg + (size_t)(kb * 64 + r) * 64 + d0;
            float4 vv4 = *(const float4*)vp;
            int swzr = ((r >> 2) & 7) << 2;
            uint4 tv = make_uint4(f2tf(vv4.x), f2tf(vv4.y), f2tf(vv4.z), f2tf(vv4.w));
            *(uint4*)&sV[r * AK_STR + (d0 ^ swzr)] = tv;
        }
        __syncthreads();

        // S = Q K^T for my 16-row strip (16 x 64)
        float sacc[8][4];
        #pragma unroll
        for (int nt = 0; nt < 8; nt++)
            #pragma unroll
            for (int e = 0; e < 4; e++) sacc[nt][e] = 0.f;

        #pragma unroll
        for (int ks = 0; ks < 64; ks += 8) {
            unsigned a[4];
            a[0] = sQ[(ks + tig) * AQ_STR + m_local];
            a[1] = sQ[(ks + tig) * AQ_STR + m_local + 8];
            a[2] = sQ[(ks + tig + 4) * AQ_STR + m_local];
            a[3] = sQ[(ks + tig + 4) * AQ_STR + m_local + 8];
            int c1 = ((ks >> 2) & 7) << 2;
            int c2 = (((ks + 4) >> 2) & 7) << 2;
            #pragma unroll
            for (int nt = 0; nt < 8; nt++) {
                int n = nt * 8 + gid;
                unsigned b0 = sK[(ks + tig) * AK_STR + (n ^ c1)];
                unsigned b1 = sK[(ks + tig + 4) * AK_STR + (n ^ c2)];
                mma8(sacc[nt], a, b0, b1);
            }
        }

        // causal mask (only the two diagonal-straddling tiles need it)
        if (kb >= 2 * qb) {
            #pragma unroll
            for (int nt = 0; nt < 8; nt++) {
                int colb = kb * 64 + nt * 8 + tig * 2;
                if (colb + 0 > row1) sacc[nt][0] = -1e30f;
                if (colb + 1 > row1) sacc[nt][1] = -1e30f;
                if (colb + 0 > row2) sacc[nt][2] = -1e30f;
                if (colb + 1 > row2) sacc[nt][3] = -1e30f;
            }
        }

        // online softmax (quad = 4 lanes covering one row)
        float mx0 = -1e30f, mx1 = -1e30f;
        #pragma unroll
        for (int nt = 0; nt < 8; nt++) {
            mx0 = fmaxf(mx0, fmaxf(sacc[nt][0], sacc[nt][1]));
            mx1 = fmaxf(mx1, fmaxf(sacc[nt][2], sacc[nt][3]));
        }
        mx0 = fmaxf(mx0, __shfl_xor_sync(0xffffffffu, mx0, 1));
        mx0 = fmaxf(mx0, __shfl_xor_sync(0xffffffffu, mx0, 2));
        mx1 = fmaxf(mx1, __shfl_xor_sync(0xffffffffu, mx1, 1));
        mx1 = fmaxf(mx1, __shfl_xor_sync(0xffffffffu, mx1, 2));

        float mn0 = fmaxf(rm0, mx0);
        float mn1 = fmaxf(rm1, mx1);
        float corr0 = __expf(rm0 - mn0);
        float corr1 = __expf(rm1 - mn1);
        rm0 = mn0; rm1 = mn1;

        float sum0 = 0.f, sum1 = 0.f;
        #pragma unroll
        for (int nt = 0; nt < 8; nt++) {
            sacc[nt][0] = __expf(sacc[nt][0] - mn0);
            sacc[nt][1] = __expf(sacc[nt][1] - mn0);
            sacc[nt][2] = __expf(sacc[nt][2] - mn1);
            sacc[nt][3] = __expf(sacc[nt][3] - mn1);
            sum0 += sacc[nt][0] + sacc[nt][1];
            sum1 += sacc[nt][2] + sacc[nt][3];
        }
        sum0 += __shfl_xor_sync(0xffffffffu, sum0, 1);
        sum0 += __shfl_xor_sync(0xffffffffu, sum0, 2);
        sum1 += __shfl_xor_sync(0xffffffffu, sum1, 1);
        sum1 += __shfl_xor_sync(0xffffffffu, sum1, 2);
        rl0 = rl0 * corr0 + sum0;
        rl1 = rl1 * corr1 + sum1;

        #pragma unroll
        for (int nt = 0; nt < 8; nt++) {
            oacc[nt][0] *= corr0; oacc[nt][1] *= corr0;
            oacc[nt][2] *= corr1; oacc[nt][3] *= corr1;
        }

        // publish P -> sP[kv][q] (tf32)
        #pragma unroll
        for (int nt = 0; nt < 8; nt++) {
            int kvc = nt * 8 + tig * 2;
            sP[(kvc + 0) * AQ_STR + m_local]     = f2tf(sacc[nt][0]);
            sP[(kvc + 1) * AQ_STR + m_local]     = f2tf(sacc[nt][1]);
            sP[(kvc + 0) * AQ_STR + m_local + 8] = f2tf(sacc[nt][2]);
            sP[(kvc + 1) * AQ_STR + m_local + 8] = f2tf(sacc[nt][3]);
        }
        __syncthreads();

        // O += P @ V   (16 x 64) += (16 x 64)(64 x 64)
        #pragma unroll
        for (int ks = 0; ks < 64; ks += 8) {
            unsigned a[4];
            a[0] = sP[(ks + tig) * AQ_STR + m_local];
            a[1] = sP[(ks + tig) * AQ_STR + m_local + 8];
            a[2] = sP[(ks + tig + 4) * AQ_STR + m_local];
            a[3] = sP[(ks + tig + 4) * AQ_STR + m_local + 8];
            int c1 = ((ks >> 2) & 7) << 2;
            int c2 = (((ks + 4) >> 2) & 7) << 2;
            #pragma unroll
            for (int nt = 0; nt < 8; nt++) {
                int n = nt * 8 + gid;
                unsigned b0 = sV[(ks + tig) * AK_STR + (n ^ c1)];
                unsigned b1 = sV[(ks + tig + 4) * AK_STR + (n ^ c2)];
                mma8(oacc[nt], a, b0, b1);
            }
        }
    }

    // epilogue: normalize, write to [B,T,C]
    int b = bh >> 4;
    int h = bh & (NH - 1);
    float il0 = 1.f / rl0;
    float il1 = 1.f / rl1;
    #pragma unroll
    for (int nt = 0; nt < 8; nt++) {
        int d = nt * 8 + tig * 2;
        *(float2*)&g_attn[((size_t)(b * TT + row1)) * CC + h * 64 + d] =
            make_float2(oacc[nt][0] * il0, oacc[nt][1] * il0);
        *(float2*)&g_attn[((size_t)(b * TT + row2)) * CC + h * 64 + d] =
            make_float2(oacc[nt][2] * il1, oacc[nt][3] * il1);
    }
}

// ---------------------------------------------------------------------------
extern "C" void kernel_launch(void* const* d_in, const int* in_sizes, int n_in,
                              void* d_out, int out_size)
{
    const float* x     = (const float*)d_in[0];
    const float* w_qkv = (const float*)d_in[1];
    const float* w_out = (const float*)d_in[2];
    float* out = (float*)d_out;

    float *qkv_p, *attn_p;
    cudaGetSymbolAddress((void**)&qkv_p,  g_qkv);
    cudaGetSymbolAddress((void**)&attn_p, g_attn);

    // 1) QKV projection: [8192,1024] @ [1024,3072]
    {
        dim3 grid(C3 / 128, BT / 128);
        gemm_tf32<<<grid, 256>>>(x, w_qkv, qkv_p, BT, C3, CC);
    }

    // 2) split + RoPE
    {
        int total = BB * NH * TT * 32;
        rope_split_kernel<<<(total + 255) / 256, 256>>>();
    }

    // 3) flash attention (tensor cores)
    {
        int smem_bytes = ATTN_SMEM_WORDS * sizeof(unsigned);
        cudaFuncSetAttribute(attn_mma_kernel,
                             cudaFuncAttributeMaxDynamicSharedMemorySize,
                             smem_bytes);
        dim3 grid(TT / 128, BB * NH);
        attn_mma_kernel<<<grid, 256, smem_bytes>>>();
    }

    // 4) output projection: [8192,1024] @ [1024,1024]
    {
        dim3 grid(CC / 128, BT / 128);
        gemm_tf32<<<grid, 256>>>(attn_p, w_out, out, BT, CC, CC);
    }
}